// round 1
// baseline (speedup 1.0000x reference)
#include <cuda_runtime.h>
#include <cuda_bf16.h>

// Problem shape (fixed by the dataset)
#define D_IN   256
#define D_OUT  512
#define NCELLS 50000

// Scratch (device globals — allocation-free rule)
__device__ float g_cell_emb[(size_t)NCELLS * D_IN];   // 51.2 MB
__device__ int   g_starts[NCELLS + 1];

// ---------------------------------------------------------------------------
// Kernel A: per-cell start offsets via lower_bound on the sorted segment_ids
// ---------------------------------------------------------------------------
__global__ void find_starts_kernel(const int* __restrict__ seg, int M, int num_cells) {
    int c = blockIdx.x * blockDim.x + threadIdx.x;
    if (c > num_cells) return;
    int lo = 0, hi = M;
    while (lo < hi) {
        int mid = (lo + hi) >> 1;
        if (seg[mid] < c) lo = mid + 1; else hi = mid;
    }
    g_starts[c] = lo;
}

// ---------------------------------------------------------------------------
// Kernel B: warp-per-cell gather + mean.
// Each lane owns 2 float4 (= 8 floats) of the 256-dim row.
// ---------------------------------------------------------------------------
__global__ void seg_mean_kernel(const float* __restrict__ feats,
                                const int* __restrict__ midx,
                                int num_cells) {
    int warp = (blockIdx.x * blockDim.x + threadIdx.x) >> 5;
    int lane = threadIdx.x & 31;
    if (warp >= num_cells) return;

    int s = g_starts[warp];
    int e = g_starts[warp + 1];

    float4 acc0 = make_float4(0.f, 0.f, 0.f, 0.f);
    float4 acc1 = make_float4(0.f, 0.f, 0.f, 0.f);

    for (int j = s; j < e; ++j) {
        const float4* row = reinterpret_cast<const float4*>(
            feats + (size_t)midx[j] * D_IN);
        float4 v0 = __ldg(&row[lane]);
        float4 v1 = __ldg(&row[lane + 32]);
        acc0.x += v0.x; acc0.y += v0.y; acc0.z += v0.z; acc0.w += v0.w;
        acc1.x += v1.x; acc1.y += v1.y; acc1.z += v1.z; acc1.w += v1.w;
    }

    int cnt = e - s;
    float inv = 1.0f / (float)(cnt > 0 ? cnt : 1);
    acc0.x *= inv; acc0.y *= inv; acc0.z *= inv; acc0.w *= inv;
    acc1.x *= inv; acc1.y *= inv; acc1.z *= inv; acc1.w *= inv;

    float4* dst = reinterpret_cast<float4*>(g_cell_emb + (size_t)warp * D_IN);
    dst[lane]      = acc0;
    dst[lane + 32] = acc1;
}

// ---------------------------------------------------------------------------
// Kernel C: SGEMM  C[M, 512] = A[M, 256] * B[256, 512] + bias
// 128x128 block tile, BK=8, 256 threads, 8x8 per-thread tile.
// ---------------------------------------------------------------------------
__global__ __launch_bounds__(256)
void sgemm_bias_kernel(const float* __restrict__ B,     // W, 256x512 row-major
                       const float* __restrict__ bias,  // 512
                       float* __restrict__ C,           // M x 512
                       int M) {
    const int BM = 128, BN = 128, BK = 8, TM = 8, TN = 8;

    __shared__ float As[BK][BM];
    __shared__ float Bs[BK][BN];

    const float* A = g_cell_emb;

    int tid = threadIdx.x;
    int tx = tid & 15;        // 0..15 -> N direction
    int ty = tid >> 4;        // 0..15 -> M direction

    int m_base = blockIdx.y * BM;
    int n_base = blockIdx.x * BN;

    // A-load mapping: one float4 per thread: row = tid/2 (0..127), col4 = tid%2
    int a_row  = tid >> 1;
    int a_col4 = tid & 1;
    // B-load mapping: one float4 per thread: row = tid/32 (0..7), col4 = tid%32
    int b_row  = tid >> 5;
    int b_col4 = tid & 31;

    float acc[TM][TN];
    #pragma unroll
    for (int i = 0; i < TM; ++i)
        #pragma unroll
        for (int j = 0; j < TN; ++j)
            acc[i][j] = 0.f;

    for (int k0 = 0; k0 < D_IN; k0 += BK) {
        // Load A tile (with M guard), store transposed As[k][m]
        float4 av = make_float4(0.f, 0.f, 0.f, 0.f);
        int gm = m_base + a_row;
        if (gm < M)
            av = *reinterpret_cast<const float4*>(
                A + (size_t)gm * D_IN + k0 + a_col4 * 4);
        As[a_col4 * 4 + 0][a_row] = av.x;
        As[a_col4 * 4 + 1][a_row] = av.y;
        As[a_col4 * 4 + 2][a_row] = av.z;
        As[a_col4 * 4 + 3][a_row] = av.w;

        // Load B tile (K=256, N=512 — no guards needed)
        float4 bv = *reinterpret_cast<const float4*>(
            B + (size_t)(k0 + b_row) * D_OUT + n_base + b_col4 * 4);
        *reinterpret_cast<float4*>(&Bs[b_row][b_col4 * 4]) = bv;

        __syncthreads();

        #pragma unroll
        for (int k = 0; k < BK; ++k) {
            float ar[TM], br[TN];
            float4 a0 = *reinterpret_cast<const float4*>(&As[k][ty * TM]);
            float4 a1 = *reinterpret_cast<const float4*>(&As[k][ty * TM + 4]);
            ar[0]=a0.x; ar[1]=a0.y; ar[2]=a0.z; ar[3]=a0.w;
            ar[4]=a1.x; ar[5]=a1.y; ar[6]=a1.z; ar[7]=a1.w;
            float4 b0 = *reinterpret_cast<const float4*>(&Bs[k][tx * TN]);
            float4 b1 = *reinterpret_cast<const float4*>(&Bs[k][tx * TN + 4]);
            br[0]=b0.x; br[1]=b0.y; br[2]=b0.z; br[3]=b0.w;
            br[4]=b1.x; br[5]=b1.y; br[6]=b1.z; br[7]=b1.w;

            #pragma unroll
            for (int i = 0; i < TM; ++i)
                #pragma unroll
                for (int j = 0; j < TN; ++j)
                    acc[i][j] += ar[i] * br[j];
        }
        __syncthreads();
    }

    // Epilogue: add bias, store (float4, with M guard)
    float4 bia0 = *reinterpret_cast<const float4*>(bias + n_base + tx * TN);
    float4 bia1 = *reinterpret_cast<const float4*>(bias + n_base + tx * TN + 4);

    #pragma unroll
    for (int i = 0; i < TM; ++i) {
        int gm = m_base + ty * TM + i;
        if (gm >= M) break;
        float4 o0, o1;
        o0.x = acc[i][0] + bia0.x; o0.y = acc[i][1] + bia0.y;
        o0.z = acc[i][2] + bia0.z; o0.w = acc[i][3] + bia0.w;
        o1.x = acc[i][4] + bia1.x; o1.y = acc[i][5] + bia1.y;
        o1.z = acc[i][6] + bia1.z; o1.w = acc[i][7] + bia1.w;
        float* dst = C + (size_t)gm * D_OUT + n_base + tx * TN;
        *reinterpret_cast<float4*>(dst)     = o0;
        *reinterpret_cast<float4*>(dst + 4) = o1;
    }
}

// ---------------------------------------------------------------------------
// Launch
// Inputs (metadata order): chunk_features, member_idx, segment_ids, num_cells, W, b
// ---------------------------------------------------------------------------
extern "C" void kernel_launch(void* const* d_in, const int* in_sizes, int n_in,
                              void* d_out, int out_size) {
    const float* feats = (const float*)d_in[0];
    const int*   midx  = (const int*)d_in[1];
    const int*   seg   = (const int*)d_in[2];
    const float* W     = (const float*)d_in[4];
    const float* bias  = (const float*)d_in[5];
    float* out = (float*)d_out;

    int M_members = in_sizes[1];
    int num_cells = out_size / D_OUT;   // 50000

    // A: segment start offsets
    {
        int n = num_cells + 1;
        find_starts_kernel<<<(n + 255) / 256, 256>>>(seg, M_members, num_cells);
    }
    // B: gather + segment mean (warp per cell)
    {
        int total_threads = num_cells * 32;
        seg_mean_kernel<<<(total_threads + 255) / 256, 256>>>(feats, midx, num_cells);
    }
    // C: projection GEMM + bias
    {
        dim3 grid(D_OUT / 128, (num_cells + 127) / 128);
        sgemm_bias_kernel<<<grid, 256>>>(W, bias, out, num_cells);
    }
}

// round 3
// speedup vs baseline: 2.2826x; 2.2826x over previous
#include <cuda_runtime.h>
#include <cuda_bf16.h>
#include <cstdint>

// Problem shape (fixed by the dataset)
#define D_IN   256
#define D_OUT  512
#define MAX_M  50048          // 391 * 128  (padded; .bss zero-init)

// GEMM tiling
#define TILE_M 128
#define TILE_N 128
#define BK     64             // bf16 per K-chunk (128 bytes per row)
#define NCHUNKS (D_IN / BK)   // 4
#define OP_BYTES  (128 * 128)        // 128 rows x 128B = 16KB per operand tile
#define STAGE_BYTES (4 * OP_BYTES)   // Ah, Al, Bh, Bl = 64KB
#define SMEM_TOTAL  (2 * STAGE_BYTES)

// ---------------------------------------------------------------------------
// Scratch (device globals — allocation-free rule)
// ---------------------------------------------------------------------------
__device__ __nv_bfloat16 g_a_hi[(size_t)MAX_M * D_IN];
__device__ __nv_bfloat16 g_a_lo[(size_t)MAX_M * D_IN];
__device__ __nv_bfloat16 g_b_hi[(size_t)D_OUT * D_IN];   // W^T [512][256]
__device__ __nv_bfloat16 g_b_lo[(size_t)D_OUT * D_IN];
__device__ int g_starts[MAX_M + 2];

// ---------------------------------------------------------------------------
// PTX helpers (legacy tensor-core path only — tcgen05 is NOT available
// through the harness's compute_103 virtual target)
// ---------------------------------------------------------------------------
__device__ __forceinline__ uint32_t smem_u32(const void* p) {
    uint32_t a;
    asm("{ .reg .u64 t; cvta.to.shared.u64 t, %1; cvt.u32.u64 %0, t; }"
        : "=r"(a) : "l"(p));
    return a;
}

#define CP_ASYNC16(dst_u32, src_ptr) \
    asm volatile("cp.async.cg.shared.global [%0], [%1], 16;" \
                 :: "r"(dst_u32), "l"(src_ptr))
#define CP_COMMIT() asm volatile("cp.async.commit_group;" ::: "memory")
#define CP_WAIT(n)  asm volatile("cp.async.wait_group %0;" :: "n"(n) : "memory")

#define LDSM_X4(r0, r1, r2, r3, addr) \
    asm volatile("ldmatrix.sync.aligned.m8n8.x4.shared.b16 {%0,%1,%2,%3}, [%4];" \
                 : "=r"(r0), "=r"(r1), "=r"(r2), "=r"(r3) : "r"(addr))

#define MMA_BF16(d, a, b) \
    asm volatile( \
        "mma.sync.aligned.m16n8k16.row.col.f32.bf16.bf16.f32 " \
        "{%0,%1,%2,%3}, {%4,%5,%6,%7}, {%8,%9}, {%0,%1,%2,%3};" \
        : "+f"((d)[0]), "+f"((d)[1]), "+f"((d)[2]), "+f"((d)[3]) \
        : "r"((a)[0]), "r"((a)[1]), "r"((a)[2]), "r"((a)[3]), \
          "r"((b)[0]), "r"((b)[1]))

// SW128-style swizzle, closed form for 128B rows:
//   sw(row*128 + col) = row*128 + (col ^ ((row & 7) * 16))
__device__ __forceinline__ uint32_t sw_off(int row, int colbyte) {
    return (uint32_t)(row * 128 + (colbyte ^ ((row & 7) << 4)));
}

// ---------------------------------------------------------------------------
// Kernel A: per-cell start offsets — scatter from member boundaries
// ---------------------------------------------------------------------------
__global__ void find_starts_kernel(const int* __restrict__ seg, int M, int num_cells) {
    int i = blockIdx.x * blockDim.x + threadIdx.x;
    if (i >= M) return;
    int cur = seg[i];
    int prev = (i == 0) ? -1 : seg[i - 1];
    for (int c = prev + 1; c <= cur; ++c) g_starts[c] = i;
    if (i == M - 1)
        for (int c = cur + 1; c <= num_cells; ++c) g_starts[c] = M;
}

// ---------------------------------------------------------------------------
// bf16 hi/lo split (4 floats -> 2x 8-byte stores)
// ---------------------------------------------------------------------------
__device__ __forceinline__ void split_store4(float4 v,
                                             __nv_bfloat16* hi,
                                             __nv_bfloat16* lo) {
    __nv_bfloat162 h01 = __floats2bfloat162_rn(v.x, v.y);
    __nv_bfloat162 h23 = __floats2bfloat162_rn(v.z, v.w);
    float rx = v.x - __low2float(h01);
    float ry = v.y - __high2float(h01);
    float rz = v.z - __low2float(h23);
    float rw = v.w - __high2float(h23);
    __nv_bfloat162 l01 = __floats2bfloat162_rn(rx, ry);
    __nv_bfloat162 l23 = __floats2bfloat162_rn(rz, rw);
    uint2 hp, lp;
    hp.x = *reinterpret_cast<uint32_t*>(&h01);
    hp.y = *reinterpret_cast<uint32_t*>(&h23);
    lp.x = *reinterpret_cast<uint32_t*>(&l01);
    lp.y = *reinterpret_cast<uint32_t*>(&l23);
    *reinterpret_cast<uint2*>(hi) = hp;
    *reinterpret_cast<uint2*>(lo) = lp;
}

// ---------------------------------------------------------------------------
// Kernel B: warp-per-cell gather + mean, fused bf16 hi/lo split epilogue
// ---------------------------------------------------------------------------
__global__ void seg_mean_kernel(const float* __restrict__ feats,
                                const int* __restrict__ midx,
                                int num_cells) {
    int warp = (blockIdx.x * blockDim.x + threadIdx.x) >> 5;
    int lane = threadIdx.x & 31;
    if (warp >= num_cells) return;

    int s = g_starts[warp];
    int e = g_starts[warp + 1];

    float4 acc0 = make_float4(0.f, 0.f, 0.f, 0.f);
    float4 acc1 = make_float4(0.f, 0.f, 0.f, 0.f);

    for (int j = s; j < e; ++j) {
        const float4* row = reinterpret_cast<const float4*>(
            feats + (size_t)__ldg(midx + j) * D_IN);
        float4 v0 = __ldg(&row[lane]);
        float4 v1 = __ldg(&row[lane + 32]);
        acc0.x += v0.x; acc0.y += v0.y; acc0.z += v0.z; acc0.w += v0.w;
        acc1.x += v1.x; acc1.y += v1.y; acc1.z += v1.z; acc1.w += v1.w;
    }

    int cnt = e - s;
    float inv = 1.0f / (float)(cnt > 0 ? cnt : 1);
    acc0.x *= inv; acc0.y *= inv; acc0.z *= inv; acc0.w *= inv;
    acc1.x *= inv; acc1.y *= inv; acc1.z *= inv; acc1.w *= inv;

    size_t base = (size_t)warp * D_IN + 4 * lane;
    split_store4(acc0, g_a_hi + base,       g_a_lo + base);
    split_store4(acc1, g_a_hi + base + 128, g_a_lo + base + 128);
}

// ---------------------------------------------------------------------------
// Kernel C: transpose + hi/lo split of W  ([256,512] fp32 -> [512,256] bf16 x2)
// ---------------------------------------------------------------------------
__global__ void convert_w_kernel(const float* __restrict__ W) {
    int idx = blockIdx.x * blockDim.x + threadIdx.x;
    if (idx >= D_IN * D_OUT) return;
    int k = idx / D_OUT;
    int n = idx - k * D_OUT;
    float v = W[idx];
    __nv_bfloat16 h = __float2bfloat16(v);
    g_b_hi[(size_t)n * D_IN + k] = h;
    g_b_lo[(size_t)n * D_IN + k] = __float2bfloat16(v - __bfloat162float(h));
}

// ---------------------------------------------------------------------------
// Kernel D: mma.sync bf16 GEMM  out[M,512] = A[M,256] @ W[256,512] + bias
// 128x128 tile / CTA, BK=64, cp.async double buffer, hi/lo 3-pass MMA.
// 8 warps: warp (wm in 0..3, wn in 0..1) computes 32(M) x 64(N).
// ---------------------------------------------------------------------------
__device__ __forceinline__ void load_stage(uint32_t stage_u32, int m_base,
                                           int n_base, int kchunk) {
    int tid = threadIdx.x;
    const char* gah = reinterpret_cast<const char*>(g_a_hi);
    const char* gal = reinterpret_cast<const char*>(g_a_lo);
    const char* gbh = reinterpret_cast<const char*>(g_b_hi);
    const char* gbl = reinterpret_cast<const char*>(g_b_lo);
    int kbyte = kchunk * BK * 2;   // byte offset of K-chunk within a 512B row
    #pragma unroll
    for (int i = 0; i < 4; ++i) {
        int seg = tid + i * 256;           // 0..1023
        int r = seg >> 3;                  // 0..127
        int cb = (seg & 7) << 4;           // 0..112, 16B steps
        uint32_t so = sw_off(r, cb);
        size_t a_src = (size_t)(m_base + r) * (D_IN * 2) + kbyte + cb;
        size_t b_src = (size_t)(n_base + r) * (D_IN * 2) + kbyte + cb;
        CP_ASYNC16(stage_u32 + 0 * OP_BYTES + so, gah + a_src);
        CP_ASYNC16(stage_u32 + 1 * OP_BYTES + so, gal + a_src);
        CP_ASYNC16(stage_u32 + 2 * OP_BYTES + so, gbh + b_src);
        CP_ASYNC16(stage_u32 + 3 * OP_BYTES + so, gbl + b_src);
    }
}

__global__ __launch_bounds__(256, 1)
void gemm_kernel(const float* __restrict__ bias, float* __restrict__ out, int M) {
    extern __shared__ char smem[];
    uint32_t sb = smem_u32(smem);

    int tid  = threadIdx.x;
    int wid  = tid >> 5;
    int lane = tid & 31;
    int wm = wid >> 1;           // 0..3  (M direction, 32 rows each)
    int wn = wid & 1;            // 0..1  (N direction, 64 cols each)

    int m_base = blockIdx.y * TILE_M;
    int n_base = blockIdx.x * TILE_N;

    float acc[2][8][4];
    #pragma unroll
    for (int mt = 0; mt < 2; ++mt)
        #pragma unroll
        for (int nt = 0; nt < 8; ++nt)
            #pragma unroll
            for (int j = 0; j < 4; ++j)
                acc[mt][nt][j] = 0.f;

    // Prologue: fill both stages
    load_stage(sb, m_base, n_base, 0);
    CP_COMMIT();
    load_stage(sb + STAGE_BYTES, m_base, n_base, 1);
    CP_COMMIT();

    // Precomputed ldmatrix lane offsets (row, colbyte-within-16B-group)
    int a_row  = wm * 32 + (lane & 15);           // + mt*16
    int a_cgrp = (lane >> 4) << 4;                // 0 or 16
    int b_m    = lane >> 3;                       // matrix idx 0..3
    int b_row  = wn * 64 + ((b_m >> 1) << 3) + (lane & 7);  // + ntp*16
    int b_cgrp = (b_m & 1) << 4;                  // 0 or 16

    for (int c = 0; c < NCHUNKS; ++c) {
        CP_WAIT(1);
        __syncthreads();

        uint32_t stage = sb + (uint32_t)(c & 1) * STAGE_BYTES;

        #pragma unroll
        for (int ks = 0; ks < 4; ++ks) {
            int kb = ks * 32;
            uint32_t ah[2][4], al[2][4];
            #pragma unroll
            for (int mt = 0; mt < 2; ++mt) {
                uint32_t off = sw_off(a_row + mt * 16, kb + a_cgrp);
                LDSM_X4(ah[mt][0], ah[mt][1], ah[mt][2], ah[mt][3],
                        stage + 0 * OP_BYTES + off);
                LDSM_X4(al[mt][0], al[mt][1], al[mt][2], al[mt][3],
                        stage + 1 * OP_BYTES + off);
            }
            uint32_t bh[8][2], bl[8][2];
            #pragma unroll
            for (int ntp = 0; ntp < 4; ++ntp) {
                uint32_t off = sw_off(b_row + ntp * 16, kb + b_cgrp);
                LDSM_X4(bh[2*ntp][0], bh[2*ntp][1], bh[2*ntp+1][0], bh[2*ntp+1][1],
                        stage + 2 * OP_BYTES + off);
                LDSM_X4(bl[2*ntp][0], bl[2*ntp][1], bl[2*ntp+1][0], bl[2*ntp+1][1],
                        stage + 3 * OP_BYTES + off);
            }
            #pragma unroll
            for (int mt = 0; mt < 2; ++mt)
                #pragma unroll
                for (int nt = 0; nt < 8; ++nt) {
                    MMA_BF16(acc[mt][nt], ah[mt], bh[nt]);
                    MMA_BF16(acc[mt][nt], ah[mt], bl[nt]);
                    MMA_BF16(acc[mt][nt], al[mt], bh[nt]);
                }
        }

        __syncthreads();    // all warps done reading this stage
        if (c + 2 < NCHUNKS) {
            load_stage(stage, m_base, n_base, c + 2);
        }
        CP_COMMIT();        // keep group count in lockstep (may be empty)
    }

    // Epilogue: bias add + guarded stores
    int g = lane >> 2;           // row within m16 tile
    int q = lane & 3;            // col pair within n8 tile
    #pragma unroll
    for (int mt = 0; mt < 2; ++mt) {
        int r0 = m_base + wm * 32 + mt * 16 + g;
        #pragma unroll
        for (int nt = 0; nt < 8; ++nt) {
            int col = n_base + wn * 64 + nt * 8 + q * 2;
            float2 bv = *reinterpret_cast<const float2*>(bias + col);
            if (r0 < M) {
                float2 o = make_float2(acc[mt][nt][0] + bv.x,
                                       acc[mt][nt][1] + bv.y);
                *reinterpret_cast<float2*>(out + (size_t)r0 * D_OUT + col) = o;
            }
            if (r0 + 8 < M) {
                float2 o = make_float2(acc[mt][nt][2] + bv.x,
                                       acc[mt][nt][3] + bv.y);
                *reinterpret_cast<float2*>(out + (size_t)(r0 + 8) * D_OUT + col) = o;
            }
        }
    }
}

// ---------------------------------------------------------------------------
// Launch
// Inputs (metadata order): chunk_features, member_idx, segment_ids, num_cells, W, b
// ---------------------------------------------------------------------------
extern "C" void kernel_launch(void* const* d_in, const int* in_sizes, int n_in,
                              void* d_out, int out_size) {
    const float* feats = (const float*)d_in[0];
    const int*   midx  = (const int*)d_in[1];
    const int*   seg   = (const int*)d_in[2];
    const float* W     = (const float*)d_in[4];
    const float* bias  = (const float*)d_in[5];
    float* out = (float*)d_out;

    int M_members = in_sizes[1];
    int num_cells = out_size / D_OUT;   // 50000

    // A: segment start offsets (scatter over member boundaries)
    find_starts_kernel<<<(M_members + 255) / 256, 256>>>(seg, M_members, num_cells);

    // B: gather + segment mean -> bf16 hi/lo (warp per cell)
    {
        int total_threads = num_cells * 32;
        seg_mean_kernel<<<(total_threads + 255) / 256, 256>>>(feats, midx, num_cells);
    }

    // C: W transpose + hi/lo split
    convert_w_kernel<<<(D_IN * D_OUT + 255) / 256, 256>>>(W);

    // D: tensor-core projection GEMM + bias (mma.sync HMMA path)
    {
        static bool attr_set = false;
        if (!attr_set) {
            cudaFuncSetAttribute(gemm_kernel,
                                 cudaFuncAttributeMaxDynamicSharedMemorySize,
                                 SMEM_TOTAL);
            attr_set = true;
        }
        dim3 grid(D_OUT / TILE_N, (num_cells + TILE_M - 1) / TILE_M);
        gemm_kernel<<<grid, 256, SMEM_TOTAL>>>(bias, out, num_cells);
    }
}

// round 4
// speedup vs baseline: 3.8235x; 1.6751x over previous
#include <cuda_runtime.h>
#include <cuda_fp16.h>
#include <cstdint>

// Problem shape (fixed by the dataset)
#define D_IN   256
#define D_OUT  512
#define MAX_M  50048          // 391 * 128  (padded; .bss zero-init)

// GEMM tiling
#define TILE_M 128
#define TILE_N 128
#define BK     64             // fp16 per K-chunk (128 bytes per row)
#define NCHUNKS (D_IN / BK)   // 4
#define OP_BYTES  (128 * 128)        // 128 rows x 128B = 16KB per operand tile
#define STAGE_BYTES (2 * OP_BYTES)   // A, B = 32KB
#define SMEM_TOTAL  (2 * STAGE_BYTES)  // 64KB

// ---------------------------------------------------------------------------
// Scratch (device globals — allocation-free rule)
// ---------------------------------------------------------------------------
__device__ __half g_a[(size_t)MAX_M * D_IN];
__device__ __half g_b[(size_t)D_OUT * D_IN];   // W^T [512][256]
__device__ int g_starts[MAX_M + 2];

// ---------------------------------------------------------------------------
// PTX helpers (legacy tensor-core path — tcgen05 NOT available through the
// harness's compute_103 virtual target)
// ---------------------------------------------------------------------------
__device__ __forceinline__ uint32_t smem_u32(const void* p) {
    uint32_t a;
    asm("{ .reg .u64 t; cvta.to.shared.u64 t, %1; cvt.u32.u64 %0, t; }"
        : "=r"(a) : "l"(p));
    return a;
}

#define CP_ASYNC16(dst_u32, src_ptr) \
    asm volatile("cp.async.cg.shared.global [%0], [%1], 16;" \
                 :: "r"(dst_u32), "l"(src_ptr))
#define CP_COMMIT() asm volatile("cp.async.commit_group;" ::: "memory")
#define CP_WAIT(n)  asm volatile("cp.async.wait_group %0;" :: "n"(n) : "memory")

#define LDSM_X4(r0, r1, r2, r3, addr) \
    asm volatile("ldmatrix.sync.aligned.m8n8.x4.shared.b16 {%0,%1,%2,%3}, [%4];" \
                 : "=r"(r0), "=r"(r1), "=r"(r2), "=r"(r3) : "r"(addr))

#define MMA_F16(d, a, b) \
    asm volatile( \
        "mma.sync.aligned.m16n8k16.row.col.f32.f16.f16.f32 " \
        "{%0,%1,%2,%3}, {%4,%5,%6,%7}, {%8,%9}, {%0,%1,%2,%3};" \
        : "+f"((d)[0]), "+f"((d)[1]), "+f"((d)[2]), "+f"((d)[3]) \
        : "r"((a)[0]), "r"((a)[1]), "r"((a)[2]), "r"((a)[3]), \
          "r"((b)[0]), "r"((b)[1]))

// SW128-style swizzle, closed form for 128B rows:
//   sw(row*128 + col) = row*128 + (col ^ ((row & 7) * 16))
__device__ __forceinline__ uint32_t sw_off(int row, int colbyte) {
    return (uint32_t)(row * 128 + (colbyte ^ ((row & 7) << 4)));
}

// ---------------------------------------------------------------------------
// Kernel A: per-cell start offsets — scatter from member boundaries
// ---------------------------------------------------------------------------
__global__ void find_starts_kernel(const int* __restrict__ seg, int M, int num_cells) {
    int i = blockIdx.x * blockDim.x + threadIdx.x;
    if (i >= M) return;
    int cur = seg[i];
    int prev = (i == 0) ? -1 : seg[i - 1];
    for (int c = prev + 1; c <= cur; ++c) g_starts[c] = i;
    if (i == M - 1)
        for (int c = cur + 1; c <= num_cells; ++c) g_starts[c] = M;
}

// ---------------------------------------------------------------------------
// Kernel B: warp-per-cell gather + mean, fp16 conversion epilogue
// ---------------------------------------------------------------------------
__global__ void seg_mean_kernel(const float* __restrict__ feats,
                                const int* __restrict__ midx,
                                int num_cells) {
    int warp = (blockIdx.x * blockDim.x + threadIdx.x) >> 5;
    int lane = threadIdx.x & 31;
    if (warp >= num_cells) return;

    int s = g_starts[warp];
    int e = g_starts[warp + 1];

    float4 acc0 = make_float4(0.f, 0.f, 0.f, 0.f);
    float4 acc1 = make_float4(0.f, 0.f, 0.f, 0.f);

    for (int j = s; j < e; ++j) {
        const float4* row = reinterpret_cast<const float4*>(
            feats + (size_t)__ldg(midx + j) * D_IN);
        float4 v0 = __ldg(&row[lane]);
        float4 v1 = __ldg(&row[lane + 32]);
        acc0.x += v0.x; acc0.y += v0.y; acc0.z += v0.z; acc0.w += v0.w;
        acc1.x += v1.x; acc1.y += v1.y; acc1.z += v1.z; acc1.w += v1.w;
    }

    int cnt = e - s;
    float inv = 1.0f / (float)(cnt > 0 ? cnt : 1);

    __half2 h0a = __floats2half2_rn(acc0.x * inv, acc0.y * inv);
    __half2 h0b = __floats2half2_rn(acc0.z * inv, acc0.w * inv);
    __half2 h1a = __floats2half2_rn(acc1.x * inv, acc1.y * inv);
    __half2 h1b = __floats2half2_rn(acc1.z * inv, acc1.w * inv);

    size_t base = (size_t)warp * D_IN + 4 * lane;
    uint2 p0, p1;
    p0.x = *reinterpret_cast<uint32_t*>(&h0a);
    p0.y = *reinterpret_cast<uint32_t*>(&h0b);
    p1.x = *reinterpret_cast<uint32_t*>(&h1a);
    p1.y = *reinterpret_cast<uint32_t*>(&h1b);
    *reinterpret_cast<uint2*>(g_a + base)       = p0;
    *reinterpret_cast<uint2*>(g_a + base + 128) = p1;
}

// ---------------------------------------------------------------------------
// Kernel C: transpose + fp16 convert of W  ([256,512] fp32 -> [512,256] fp16)
// ---------------------------------------------------------------------------
__global__ void convert_w_kernel(const float* __restrict__ W) {
    int idx = blockIdx.x * blockDim.x + threadIdx.x;
    if (idx >= D_IN * D_OUT) return;
    int k = idx / D_OUT;
    int n = idx - k * D_OUT;
    g_b[(size_t)n * D_IN + k] = __float2half(W[idx]);
}

// ---------------------------------------------------------------------------
// Kernel D: mma.sync fp16 GEMM  out[M,512] = A[M,256] @ W[256,512] + bias
// 128x128 tile / CTA, BK=64, cp.async double buffer, single fp16 pass.
// 8 warps: warp (wm in 0..3, wn in 0..1) computes 32(M) x 64(N).
// 2 CTAs/SM (64KB smem, <=128 regs).
// ---------------------------------------------------------------------------
__device__ __forceinline__ void load_stage(uint32_t stage_u32, int m_base,
                                           int n_base, int kchunk) {
    int tid = threadIdx.x;
    const char* gA = reinterpret_cast<const char*>(g_a);
    const char* gB = reinterpret_cast<const char*>(g_b);
    int kbyte = kchunk * BK * 2;   // byte offset of K-chunk within a 512B row
    #pragma unroll
    for (int i = 0; i < 4; ++i) {
        int seg = tid + i * 256;           // 0..1023
        int r = seg >> 3;                  // 0..127
        int cb = (seg & 7) << 4;           // 0..112, 16B steps
        uint32_t so = sw_off(r, cb);
        CP_ASYNC16(stage_u32 + so,
                   gA + (size_t)(m_base + r) * (D_IN * 2) + kbyte + cb);
        CP_ASYNC16(stage_u32 + OP_BYTES + so,
                   gB + (size_t)(n_base + r) * (D_IN * 2) + kbyte + cb);
    }
}

__global__ __launch_bounds__(256, 2)
void gemm_kernel(const float* __restrict__ bias, float* __restrict__ out, int M) {
    extern __shared__ char smem[];
    uint32_t sb = smem_u32(smem);

    int tid  = threadIdx.x;
    int wid  = tid >> 5;
    int lane = tid & 31;
    int wm = wid >> 1;           // 0..3  (M direction, 32 rows each)
    int wn = wid & 1;            // 0..1  (N direction, 64 cols each)

    int m_base = blockIdx.y * TILE_M;
    int n_base = blockIdx.x * TILE_N;

    float acc[2][8][4];
    #pragma unroll
    for (int mt = 0; mt < 2; ++mt)
        #pragma unroll
        for (int nt = 0; nt < 8; ++nt)
            #pragma unroll
            for (int j = 0; j < 4; ++j)
                acc[mt][nt][j] = 0.f;

    // Prologue: fill both stages
    load_stage(sb, m_base, n_base, 0);
    CP_COMMIT();
    load_stage(sb + STAGE_BYTES, m_base, n_base, 1);
    CP_COMMIT();

    // ldmatrix lane offsets
    int a_row  = wm * 32 + (lane & 15);                     // + mt*16
    int a_cgrp = (lane >> 4) << 4;                          // 0 or 16
    int b_m    = lane >> 3;                                 // matrix idx 0..3
    int b_row  = wn * 64 + ((b_m >> 1) << 3) + (lane & 7);  // + ntp*16
    int b_cgrp = (b_m & 1) << 4;                            // 0 or 16

    for (int c = 0; c < NCHUNKS; ++c) {
        CP_WAIT(1);
        __syncthreads();

        uint32_t stage = sb + (uint32_t)(c & 1) * STAGE_BYTES;

        #pragma unroll
        for (int ks = 0; ks < 4; ++ks) {
            int kb = ks * 32;
            uint32_t a[2][4];
            #pragma unroll
            for (int mt = 0; mt < 2; ++mt) {
                uint32_t off = sw_off(a_row + mt * 16, kb + a_cgrp);
                LDSM_X4(a[mt][0], a[mt][1], a[mt][2], a[mt][3], stage + off);
            }
            uint32_t b[8][2];
            #pragma unroll
            for (int ntp = 0; ntp < 4; ++ntp) {
                uint32_t off = sw_off(b_row + ntp * 16, kb + b_cgrp);
                LDSM_X4(b[2*ntp][0], b[2*ntp][1], b[2*ntp+1][0], b[2*ntp+1][1],
                        stage + OP_BYTES + off);
            }
            #pragma unroll
            for (int mt = 0; mt < 2; ++mt)
                #pragma unroll
                for (int nt = 0; nt < 8; ++nt)
                    MMA_F16(acc[mt][nt], a[mt], b[nt]);
        }

        __syncthreads();    // all warps done reading this stage
        if (c + 2 < NCHUNKS) {
            load_stage(stage, m_base, n_base, c + 2);
        }
        CP_COMMIT();        // keep group count in lockstep (may be empty)
    }

    // Epilogue: bias add + guarded stores
    int g = lane >> 2;           // row within m16 tile
    int q = lane & 3;            // col pair within n8 tile
    #pragma unroll
    for (int mt = 0; mt < 2; ++mt) {
        int r0 = m_base + wm * 32 + mt * 16 + g;
        #pragma unroll
        for (int nt = 0; nt < 8; ++nt) {
            int col = n_base + wn * 64 + nt * 8 + q * 2;
            float2 bv = *reinterpret_cast<const float2*>(bias + col);
            if (r0 < M) {
                float2 o = make_float2(acc[mt][nt][0] + bv.x,
                                       acc[mt][nt][1] + bv.y);
                *reinterpret_cast<float2*>(out + (size_t)r0 * D_OUT + col) = o;
            }
            if (r0 + 8 < M) {
                float2 o = make_float2(acc[mt][nt][2] + bv.x,
                                       acc[mt][nt][3] + bv.y);
                *reinterpret_cast<float2*>(out + (size_t)(r0 + 8) * D_OUT + col) = o;
            }
        }
    }
}

// ---------------------------------------------------------------------------
// Launch
// Inputs (metadata order): chunk_features, member_idx, segment_ids, num_cells, W, b
// ---------------------------------------------------------------------------
extern "C" void kernel_launch(void* const* d_in, const int* in_sizes, int n_in,
                              void* d_out, int out_size) {
    const float* feats = (const float*)d_in[0];
    const int*   midx  = (const int*)d_in[1];
    const int*   seg   = (const int*)d_in[2];
    const float* W     = (const float*)d_in[4];
    const float* bias  = (const float*)d_in[5];
    float* out = (float*)d_out;

    int M_members = in_sizes[1];
    int num_cells = out_size / D_OUT;   // 50000

    // A: segment start offsets (scatter over member boundaries)
    find_starts_kernel<<<(M_members + 255) / 256, 256>>>(seg, M_members, num_cells);

    // B: gather + segment mean -> fp16 A (warp per cell)
    {
        int total_threads = num_cells * 32;
        seg_mean_kernel<<<(total_threads + 255) / 256, 256>>>(feats, midx, num_cells);
    }

    // C: W transpose + fp16 convert
    convert_w_kernel<<<(D_IN * D_OUT + 255) / 256, 256>>>(W);

    // D: tensor-core projection GEMM + bias (mma.sync HMMA fp16 path)
    {
        static bool attr_set = false;
        if (!attr_set) {
            cudaFuncSetAttribute(gemm_kernel,
                                 cudaFuncAttributeMaxDynamicSharedMemorySize,
                                 SMEM_TOTAL);
            attr_set = true;
        }
        dim3 grid(D_OUT / TILE_N, (num_cells + TILE_M - 1) / TILE_M);
        gemm_kernel<<<grid, 256, SMEM_TOTAL>>>(bias, out, num_cells);
    }
}